// round 4
// baseline (speedup 1.0000x reference)
#include <cuda_runtime.h>
#include <cstdint>
#include <math.h>

// Problem constants
#define NUM_E   16
#define T_TOK   8192
#define DIN     1024
#define DOUT    4096
#define TPE     512        // tokens per expert (balanced)

// GEMM tiling
#define BM 128
#define BN 128
#define BK 32
#define KIT (DIN / BK)     // 32 k-iterations
#define NSTAGE 3
#define STAGE_BYTES 32768  // A 16KB + B 16KB
#define SMEM_TOTAL (NSTAGE * STAGE_BYTES)

// 32MB scratch for LayerNorm output (allocation-free rule: __device__ global)
__device__ float g_xn[(size_t)T_TOK * DIN];

// ---------------- helpers ----------------
__device__ __forceinline__ uint32_t smem_u32(const void* p) {
    uint32_t a;
    asm("{ .reg .u64 t; cvta.to.shared.u64 t, %1; cvt.u32.u64 %0, t; }"
        : "=r"(a) : "l"(p));
    return a;
}

#define CP_ASYNC16(dst, src) \
    asm volatile("cp.async.cg.shared.global [%0], [%1], 16;" \
        :: "r"(dst), "l"(src))
#define CP_COMMIT() asm volatile("cp.async.commit_group;" ::: "memory")
#define CP_WAIT1()  asm volatile("cp.async.wait_group 1;" ::: "memory")

__device__ __forceinline__ void mma_tf32(float* d, const uint32_t* a, const uint32_t* b) {
    asm volatile(
        "mma.sync.aligned.m16n8k8.row.col.f32.tf32.tf32.f32 "
        "{%0,%1,%2,%3}, {%4,%5,%6,%7}, {%8,%9}, {%0,%1,%2,%3};"
        : "+f"(d[0]), "+f"(d[1]), "+f"(d[2]), "+f"(d[3])
        : "r"(a[0]), "r"(a[1]), "r"(a[2]), "r"(a[3]), "r"(b[0]), "r"(b[1]));
}

__device__ __forceinline__ float tanh_fast(float x) {
    float r;
    asm("tanh.approx.f32 %0, %1;" : "=f"(r) : "f"(x));
    return r;
}

// tanh-GELU (matches jax.nn.gelu approximate=True)
__device__ __forceinline__ float gelu_tanh(float x) {
    const float c = 0.7978845608028654f;
    float t = tanh_fast(c * (x + 0.044715f * x * x * x));
    return 0.5f * x * (1.0f + t);
}

__device__ __forceinline__ float round_tf32(float x) {
    uint32_t u;
    asm("cvt.rna.tf32.f32 %0, %1;" : "=r"(u) : "f"(x));
    return __uint_as_float(u);
}

// ---------------- LayerNorm kernel (outputs tf32-rounded fp32) ----------------
__global__ __launch_bounds__(256) void ln_kernel(
    const float* __restrict__ x,
    const float* __restrict__ gamma,
    const float* __restrict__ beta)
{
    __shared__ float red[18];
    const int t = blockIdx.x;
    const int tid = threadIdx.x;

    const float4 v = reinterpret_cast<const float4*>(x + (size_t)t * DIN)[tid];
    float s = v.x + v.y + v.z + v.w;
    float q = v.x * v.x + v.y * v.y + v.z * v.z + v.w * v.w;
    #pragma unroll
    for (int o = 16; o; o >>= 1) {
        s += __shfl_xor_sync(0xFFFFFFFFu, s, o);
        q += __shfl_xor_sync(0xFFFFFFFFu, q, o);
    }
    if ((tid & 31) == 0) { red[tid >> 5] = s; red[8 + (tid >> 5)] = q; }
    __syncthreads();
    if (tid < 32) {
        float ts = (tid < 8) ? red[tid] : 0.0f;
        float tq = (tid < 8) ? red[8 + tid] : 0.0f;
        #pragma unroll
        for (int o = 4; o; o >>= 1) {
            ts += __shfl_xor_sync(0xFFFFFFFFu, ts, o);
            tq += __shfl_xor_sync(0xFFFFFFFFu, tq, o);
        }
        if (tid == 0) { red[16] = ts; red[17] = tq; }
    }
    __syncthreads();
    const float mean = red[16] * (1.0f / DIN);
    const float var  = red[17] * (1.0f / DIN) - mean * mean;
    const float rs   = rsqrtf(var + 1e-5f);

    const int e = t >> 9;
    const float4 g  = reinterpret_cast<const float4*>(gamma + (size_t)e * DIN)[tid];
    const float4 bb = reinterpret_cast<const float4*>(beta  + (size_t)e * DIN)[tid];
    float4 o;
    o.x = round_tf32((v.x - mean) * rs * g.x + bb.x);
    o.y = round_tf32((v.y - mean) * rs * g.y + bb.y);
    o.z = round_tf32((v.z - mean) * rs * g.z + bb.z);
    o.w = round_tf32((v.w - mean) * rs * g.w + bb.w);
    reinterpret_cast<float4*>(g_xn + (size_t)t * DIN)[tid] = o;
}

// ---------------- cp.async stage loader ----------------
// A smem: [128 m][32 k] fp32, 128B rows, 16B chunk swizzle: chunk' = chunk ^ (m&7)
// B smem: [32 k][128 n] fp32, 512B rows, 16B chunk swizzle: chunk' = chunk ^ (k&7)
__device__ __forceinline__ void issue_stage(uint32_t sA, uint32_t sB,
                                            const float* __restrict__ xa,
                                            const float* __restrict__ wb,
                                            int k0, int tid)
{
    #pragma unroll
    for (int i = 0; i < 4; ++i) {
        const int gch = tid + i * 256;          // 0..1023
        const int m  = gch >> 3;
        const int ca = gch & 7;                 // 16B chunk within 128B row
        const float* src = xa + (size_t)m * DIN + k0 + ca * 4;
        const uint32_t dst = sA + (uint32_t)(m * 128) +
                             (uint32_t)((ca ^ (m & 7)) << 4);
        CP_ASYNC16(dst, src);
    }
    #pragma unroll
    for (int i = 0; i < 4; ++i) {
        const int gch = tid + i * 256;
        const int k  = gch >> 5;
        const int cb = gch & 31;                // 16B chunk within 512B row
        const float* src = wb + (size_t)(k0 + k) * DOUT + cb * 4;
        const uint32_t dst = sB + (uint32_t)(k * 512) +
                             (uint32_t)((cb ^ (k & 7)) << 4);
        CP_ASYNC16(dst, src);
    }
}

// ---------------- grouped GEMM + bias + GELU (tf32 mma.sync) ----------------
__global__ __launch_bounds__(256) void moe_gemm_kernel(
    const float* __restrict__ W,
    const float* __restrict__ bias,
    float* __restrict__ out)
{
    extern __shared__ char smem[];
    const uint32_t sbase = smem_u32(smem);

    const int tid  = threadIdx.x;
    const int wid  = tid >> 5;
    const int lane = tid & 31;
    const int g    = lane >> 2;   // group id 0..7
    const int c    = lane & 3;    // thread-in-group 0..3

    // warp arrangement: 2 (m) x 4 (n); warp tile 64x32
    const int warp_m = (wid >> 2) * 64;
    const int warp_n = (wid & 3) * 32;

    // CTA mapping: mt fastest so the 4 CTAs sharing a W column-slice co-run
    const int bid = blockIdx.x;                 // 0..2047
    const int e   = bid >> 7;
    const int r   = bid & 127;
    const int mt_ = r & 3;
    const int nt_ = r >> 2;
    const int tok0 = e * TPE + mt_ * BM;
    const int n0   = nt_ * BN;

    const float* xa = g_xn + (size_t)tok0 * DIN;
    const float* wb = W + (size_t)e * DIN * DOUT + n0;

    float acc[4][4][4];
    #pragma unroll
    for (int i = 0; i < 4; ++i)
        #pragma unroll
        for (int j = 0; j < 4; ++j)
            #pragma unroll
            for (int k = 0; k < 4; ++k)
                acc[i][j][k] = 0.0f;

    // prologue: stages 0 and 1
    issue_stage(sbase + 0 * STAGE_BYTES, sbase + 0 * STAGE_BYTES + 16384, xa, wb, 0, tid);
    CP_COMMIT();
    issue_stage(sbase + 1 * STAGE_BYTES, sbase + 1 * STAGE_BYTES + 16384, xa, wb, BK, tid);
    CP_COMMIT();
    CP_WAIT1();
    __syncthreads();

    for (int it = 0; it < KIT; ++it) {
        // prefetch stage it+2 (overwrites buffer consumed at it-1; safe past last sync)
        if (it + 2 < KIT) {
            const uint32_t sb2 = sbase + (uint32_t)(((it + 2) % NSTAGE) * STAGE_BYTES);
            issue_stage(sb2, sb2 + 16384, xa, wb, (it + 2) * BK, tid);
        }
        CP_COMMIT();

        const char* sA = smem + (it % NSTAGE) * STAGE_BYTES;
        const char* sB = sA + 16384;

        #pragma unroll
        for (int kk = 0; kk < 4; ++kk) {
            uint32_t afr[4][4];
            #pragma unroll
            for (int mt = 0; mt < 4; ++mt) {
                const int m0 = warp_m + mt * 16 + g;
                const int m1 = m0 + 8;
                const int ch0 = 2 * kk;          // (kk*8 + c) >> 2, c<4
                const int ch1 = 2 * kk + 1;      // (kk*8 + c+4) >> 2
                afr[mt][0] = *(const uint32_t*)(sA + m0 * 128 + ((ch0 ^ (m0 & 7)) << 4) + c * 4);
                afr[mt][1] = *(const uint32_t*)(sA + m1 * 128 + ((ch0 ^ (m1 & 7)) << 4) + c * 4);
                afr[mt][2] = *(const uint32_t*)(sA + m0 * 128 + ((ch1 ^ (m0 & 7)) << 4) + c * 4);
                afr[mt][3] = *(const uint32_t*)(sA + m1 * 128 + ((ch1 ^ (m1 & 7)) << 4) + c * 4);
            }
            uint32_t bfr[4][2];
            #pragma unroll
            for (int nt = 0; nt < 4; ++nt) {
                const int n  = warp_n + nt * 8 + g;
                const int k0q = kk * 8 + c;          // b0 row (k0q & 7 == c)
                const int k1q = k0q + 4;             // b1 row (k1q & 7 == c+4)
                bfr[nt][0] = *(const uint32_t*)(sB + k0q * 512 + (((n >> 2) ^ c) << 4) + (n & 3) * 4);
                bfr[nt][1] = *(const uint32_t*)(sB + k1q * 512 + (((n >> 2) ^ (c + 4)) << 4) + (n & 3) * 4);
            }
            #pragma unroll
            for (int mt = 0; mt < 4; ++mt)
                #pragma unroll
                for (int nt = 0; nt < 4; ++nt)
                    mma_tf32(acc[mt][nt], afr[mt], bfr[nt]);
        }

        CP_WAIT1();
        __syncthreads();
    }

    // ---------------- epilogue: bias + tanh-GELU + store ----------------
    const float* bptr = bias + (size_t)e * DOUT + n0 + warp_n;
    float2 bv[4];
    #pragma unroll
    for (int nt = 0; nt < 4; ++nt)
        bv[nt] = *(const float2*)(bptr + nt * 8 + 2 * c);

    #pragma unroll
    for (int mt = 0; mt < 4; ++mt) {
        const int row0 = tok0 + warp_m + mt * 16 + g;
        float* o0 = out + (size_t)row0 * DOUT + n0 + warp_n;
        float* o1 = o0 + (size_t)8 * DOUT;
        #pragma unroll
        for (int nt = 0; nt < 4; ++nt) {
            float2 v0, v1;
            v0.x = gelu_tanh(acc[mt][nt][0] + bv[nt].x);
            v0.y = gelu_tanh(acc[mt][nt][1] + bv[nt].y);
            v1.x = gelu_tanh(acc[mt][nt][2] + bv[nt].x);
            v1.y = gelu_tanh(acc[mt][nt][3] + bv[nt].y);
            *(float2*)(o0 + nt * 8 + 2 * c) = v0;
            *(float2*)(o1 + nt * 8 + 2 * c) = v1;
        }
    }
}

// ---------------- launch ----------------
extern "C" void kernel_launch(void* const* d_in, const int* in_sizes, int n_in,
                              void* d_out, int out_size) {
    (void)in_sizes; (void)n_in; (void)out_size;
    const float* x     = (const float*)d_in[0];
    // d_in[1] = expert_frequency (balanced, unused — reference ignores it too)
    const float* gamma = (const float*)d_in[2];
    const float* beta  = (const float*)d_in[3];
    const float* W     = (const float*)d_in[4];
    const float* b     = (const float*)d_in[5];
    float* out = (float*)d_out;

    cudaFuncSetAttribute(moe_gemm_kernel,
                         cudaFuncAttributeMaxDynamicSharedMemorySize, SMEM_TOTAL);

    ln_kernel<<<T_TOK, 256>>>(x, gamma, beta);
    moe_gemm_kernel<<<NUM_E * 4 * 32, 256, SMEM_TOTAL>>>(W, b, out);
}

// round 5
// speedup vs baseline: 1.3234x; 1.3234x over previous
#include <cuda_runtime.h>
#include <cuda_fp16.h>
#include <cstdint>
#include <math.h>

// Problem constants
#define NUM_E   16
#define T_TOK   8192
#define DIN     1024
#define DOUT    4096
#define TPE     512

// GEMM tiling
#define BM 128
#define BN 128
#define BK 32
#define KIT (DIN / BK)       // 32
#define NSTAGE 4

// SMEM stage layout (fp16, pad-stride conflict-free, no swizzle)
#define A_STRIDE 80          // bytes per m-row (32 halves = 64B + 16B pad) -> 5 mod 8 units
#define B_STRIDE 272         // bytes per k-row (128 halves = 256B + 16B pad) -> 17 mod 8 units
#define AH_BYTES (BM * A_STRIDE)          // 10240
#define BH_BYTES (BK * B_STRIDE)          // 8704
#define STAGE_BYTES (AH_BYTES + BH_BYTES) // 18944 (128B aligned)
#define SMEM_TOTAL (NSTAGE * STAGE_BYTES) // 75776

// Scratch (allocation-free rule: __device__ globals)
__device__ __half g_xh[(size_t)T_TOK * DIN];            // 16MB  LN output fp16
__device__ __half g_wh[(size_t)NUM_E * DIN * DOUT];     // 128MB W fp16

// ---------------- helpers ----------------
__device__ __forceinline__ uint32_t smem_u32(const void* p) {
    uint32_t a;
    asm("{ .reg .u64 t; cvta.to.shared.u64 t, %1; cvt.u32.u64 %0, t; }"
        : "=r"(a) : "l"(p));
    return a;
}

#define CP_ASYNC16(dst, src) \
    asm volatile("cp.async.cg.shared.global [%0], [%1], 16;" \
        :: "r"(dst), "l"(src))
#define CP_COMMIT() asm volatile("cp.async.commit_group;" ::: "memory")
#define CP_WAIT2()  asm volatile("cp.async.wait_group 2;" ::: "memory")

#define LDMATRIX_X4(r0, r1, r2, r3, addr) \
    asm volatile("ldmatrix.sync.aligned.m8n8.x4.shared.b16 {%0,%1,%2,%3}, [%4];" \
        : "=r"(r0), "=r"(r1), "=r"(r2), "=r"(r3) : "r"(addr))
#define LDMATRIX_X4_T(r0, r1, r2, r3, addr) \
    asm volatile("ldmatrix.sync.aligned.m8n8.x4.trans.shared.b16 {%0,%1,%2,%3}, [%4];" \
        : "=r"(r0), "=r"(r1), "=r"(r2), "=r"(r3) : "r"(addr))

__device__ __forceinline__ void mma_f16(float* d, const uint32_t* a, const uint32_t* b) {
    asm volatile(
        "mma.sync.aligned.m16n8k16.row.col.f32.f16.f16.f32 "
        "{%0,%1,%2,%3}, {%4,%5,%6,%7}, {%8,%9}, {%0,%1,%2,%3};"
        : "+f"(d[0]), "+f"(d[1]), "+f"(d[2]), "+f"(d[3])
        : "r"(a[0]), "r"(a[1]), "r"(a[2]), "r"(a[3]), "r"(b[0]), "r"(b[1]));
}

__device__ __forceinline__ float tanh_fast(float x) {
    float r;
    asm("tanh.approx.f32 %0, %1;" : "=f"(r) : "f"(x));
    return r;
}
__device__ __forceinline__ float gelu_tanh(float x) {
    const float c = 0.7978845608028654f;
    float t = tanh_fast(c * (x + 0.044715f * x * x * x));
    return 0.5f * x * (1.0f + t);
}

// ---------------- LayerNorm kernel -> fp16 ----------------
__global__ __launch_bounds__(256) void ln_kernel(
    const float* __restrict__ x,
    const float* __restrict__ gamma,
    const float* __restrict__ beta)
{
    __shared__ float red[18];
    const int t = blockIdx.x;
    const int tid = threadIdx.x;

    const float4 v = reinterpret_cast<const float4*>(x + (size_t)t * DIN)[tid];
    float s = v.x + v.y + v.z + v.w;
    float q = v.x * v.x + v.y * v.y + v.z * v.z + v.w * v.w;
    #pragma unroll
    for (int o = 16; o; o >>= 1) {
        s += __shfl_xor_sync(0xFFFFFFFFu, s, o);
        q += __shfl_xor_sync(0xFFFFFFFFu, q, o);
    }
    if ((tid & 31) == 0) { red[tid >> 5] = s; red[8 + (tid >> 5)] = q; }
    __syncthreads();
    if (tid < 32) {
        float ts = (tid < 8) ? red[tid] : 0.0f;
        float tq = (tid < 8) ? red[8 + tid] : 0.0f;
        #pragma unroll
        for (int o = 4; o; o >>= 1) {
            ts += __shfl_xor_sync(0xFFFFFFFFu, ts, o);
            tq += __shfl_xor_sync(0xFFFFFFFFu, tq, o);
        }
        if (tid == 0) { red[16] = ts; red[17] = tq; }
    }
    __syncthreads();
    const float mean = red[16] * (1.0f / DIN);
    const float var  = red[17] * (1.0f / DIN) - mean * mean;
    const float rs   = rsqrtf(var + 1e-5f);

    const int e = t >> 9;
    const float4 g  = reinterpret_cast<const float4*>(gamma + (size_t)e * DIN)[tid];
    const float4 bb = reinterpret_cast<const float4*>(beta  + (size_t)e * DIN)[tid];
    __half2 h0 = __floats2half2_rn((v.x - mean) * rs * g.x + bb.x,
                                   (v.y - mean) * rs * g.y + bb.y);
    __half2 h1 = __floats2half2_rn((v.z - mean) * rs * g.z + bb.z,
                                   (v.w - mean) * rs * g.w + bb.w);
    uint2 pack;
    pack.x = *reinterpret_cast<uint32_t*>(&h0);
    pack.y = *reinterpret_cast<uint32_t*>(&h1);
    reinterpret_cast<uint2*>(g_xh + (size_t)t * DIN)[tid] = pack;
}

// ---------------- W fp32 -> fp16 conversion ----------------
__global__ __launch_bounds__(256) void wcvt_kernel(const float* __restrict__ W)
{
    const size_t idx = (size_t)blockIdx.x * 256 + threadIdx.x;  // one float4 each
    const float4 v = reinterpret_cast<const float4*>(W)[idx];
    __half2 h0 = __floats2half2_rn(v.x, v.y);
    __half2 h1 = __floats2half2_rn(v.z, v.w);
    uint2 pack;
    pack.x = *reinterpret_cast<uint32_t*>(&h0);
    pack.y = *reinterpret_cast<uint32_t*>(&h1);
    reinterpret_cast<uint2*>(g_wh)[idx] = pack;
}

// ---------------- cp.async stage loader (fp16 tiles) ----------------
__device__ __forceinline__ void issue_stage(uint32_t su,
                                            const __half* __restrict__ xa,
                                            const __half* __restrict__ wb,
                                            int k0, int tid)
{
    // A: 128 m-rows x 32 k halves (64B payload per row), 512 chunks of 16B
    #pragma unroll
    for (int i = 0; i < 2; ++i) {
        const int c = tid + i * 256;
        const int m  = c >> 2;
        const int kc = c & 3;
        const __half* src = xa + (size_t)m * DIN + k0 + kc * 8;
        CP_ASYNC16(su + (uint32_t)(m * A_STRIDE + kc * 16), src);
    }
    // B: 32 k-rows x 128 n halves (256B payload per row), 512 chunks of 16B
    #pragma unroll
    for (int i = 0; i < 2; ++i) {
        const int c = tid + i * 256;
        const int k  = c >> 4;
        const int cn = c & 15;
        const __half* src = wb + (size_t)(k0 + k) * DOUT + cn * 8;
        CP_ASYNC16(su + AH_BYTES + (uint32_t)(k * B_STRIDE + cn * 16), src);
    }
}

// ---------------- grouped GEMM fp16 + bias + GELU ----------------
__global__ __launch_bounds__(256, 2) void moe_gemm_kernel(
    const float* __restrict__ bias,
    float* __restrict__ out)
{
    extern __shared__ char smem[];
    const uint32_t sbase = smem_u32(smem);

    const int tid  = threadIdx.x;
    const int wid  = tid >> 5;
    const int lane = tid & 31;
    const int g    = lane >> 2;
    const int c    = lane & 3;

    // warps: 2 (m) x 4 (n); warp tile 64x32
    const int warp_m = (wid >> 2) * 64;
    const int warp_n = (wid & 3) * 32;

    // CTA map: mt fastest (4 CTAs share each W column slice via L2)
    const int bid = blockIdx.x;
    const int e   = bid >> 7;
    const int r   = bid & 127;
    const int mt_ = r & 3;
    const int nt_ = r >> 2;
    const int tok0 = e * TPE + mt_ * BM;
    const int n0   = nt_ * BN;

    const __half* xa = g_xh + (size_t)tok0 * DIN;
    const __half* wb = g_wh + (size_t)e * DIN * DOUT + n0;

    // per-lane ldmatrix offsets (byte offsets within tile)
    const int lmat = lane >> 3;        // matrix id 0..3
    const int lrow = lane & 7;
    // A x4: mat {0,1}: m rows 0-7 / 8-15 at k0-7; mat {2,3}: same rows at k8-15
    const uint32_t aoff = (uint32_t)(((lmat & 1) * 8 + lrow) * A_STRIDE + (lmat >> 1) * 16);
    // B x4.trans: mat {0,1}: k 0-7 / 8-15 at n0-7; mat {2,3}: same at n8-15
    const uint32_t boff = (uint32_t)(((lmat & 1) * 8 + lrow) * B_STRIDE + (lmat >> 1) * 16);

    float acc[4][4][4];
    #pragma unroll
    for (int i = 0; i < 4; ++i)
        #pragma unroll
        for (int j = 0; j < 4; ++j)
            #pragma unroll
            for (int k = 0; k < 4; ++k)
                acc[i][j][k] = 0.0f;

    // prologue: stages 0..2
    #pragma unroll
    for (int s = 0; s < 3; ++s) {
        issue_stage(sbase + s * STAGE_BYTES, xa, wb, s * BK, tid);
        CP_COMMIT();
    }
    CP_WAIT2();        // stage 0 landed
    __syncthreads();

    for (int it = 0; it < KIT; ++it) {
        if (it + 3 < KIT)
            issue_stage(sbase + (uint32_t)(((it + 3) & 3) * STAGE_BYTES),
                        xa, wb, (it + 3) * BK, tid);
        CP_COMMIT();

        const uint32_t su  = sbase + (uint32_t)((it & 3) * STAGE_BYTES);
        const uint32_t suA = su + (uint32_t)(warp_m * A_STRIDE) + aoff;
        const uint32_t suB = su + AH_BYTES + (uint32_t)(warp_n * 2) + boff;

        #pragma unroll
        for (int ks = 0; ks < 2; ++ks) {
            uint32_t afr[4][4];
            #pragma unroll
            for (int mt = 0; mt < 4; ++mt)
                LDMATRIX_X4(afr[mt][0], afr[mt][1], afr[mt][2], afr[mt][3],
                            suA + (uint32_t)(mt * 16 * A_STRIDE + ks * 32));
            uint32_t bfr[2][4];
            #pragma unroll
            for (int nb = 0; nb < 2; ++nb)
                LDMATRIX_X4_T(bfr[nb][0], bfr[nb][1], bfr[nb][2], bfr[nb][3],
                              suB + (uint32_t)(ks * 16 * B_STRIDE + nb * 32));
            #pragma unroll
            for (int mt = 0; mt < 4; ++mt)
                #pragma unroll
                for (int nt = 0; nt < 4; ++nt)
                    mma_f16(acc[mt][nt], afr[mt], &bfr[nt >> 1][(nt & 1) * 2]);
        }

        CP_WAIT2();    // stage it+1 landed
        __syncthreads();
    }

    // ---------------- epilogue: bias + tanh-GELU + store ----------------
    const float* bptr = bias + (size_t)e * DOUT + n0 + warp_n;
    float2 bv[4];
    #pragma unroll
    for (int nt = 0; nt < 4; ++nt)
        bv[nt] = *(const float2*)(bptr + nt * 8 + 2 * c);

    #pragma unroll
    for (int mt = 0; mt < 4; ++mt) {
        const int row0 = tok0 + warp_m + mt * 16 + g;
        float* o0 = out + (size_t)row0 * DOUT + n0 + warp_n;
        float* o1 = o0 + (size_t)8 * DOUT;
        #pragma unroll
        for (int nt = 0; nt < 4; ++nt) {
            float2 v0, v1;
            v0.x = gelu_tanh(acc[mt][nt][0] + bv[nt].x);
            v0.y = gelu_tanh(acc[mt][nt][1] + bv[nt].y);
            v1.x = gelu_tanh(acc[mt][nt][2] + bv[nt].x);
            v1.y = gelu_tanh(acc[mt][nt][3] + bv[nt].y);
            *(float2*)(o0 + nt * 8 + 2 * c) = v0;
            *(float2*)(o1 + nt * 8 + 2 * c) = v1;
        }
    }
}

// ---------------- launch ----------------
extern "C" void kernel_launch(void* const* d_in, const int* in_sizes, int n_in,
                              void* d_out, int out_size) {
    (void)in_sizes; (void)n_in; (void)out_size;
    const float* x     = (const float*)d_in[0];
    // d_in[1] = expert_frequency (balanced; reference ignores it too)
    const float* gamma = (const float*)d_in[2];
    const float* beta  = (const float*)d_in[3];
    const float* W     = (const float*)d_in[4];
    const float* b     = (const float*)d_in[5];
    float* out = (float*)d_out;

    cudaFuncSetAttribute(moe_gemm_kernel,
                         cudaFuncAttributeMaxDynamicSharedMemorySize, SMEM_TOTAL);

    ln_kernel<<<T_TOK, 256>>>(x, gamma, beta);
    // 16 * 1024 * 4096 floats / 4 per thread / 256 per block = 65536 blocks
    wcvt_kernel<<<65536, 256>>>(W);
    moe_gemm_kernel<<<NUM_E * 4 * 32, 256, SMEM_TOTAL>>>(b, out);
}

// round 6
// speedup vs baseline: 1.5077x; 1.1393x over previous
#include <cuda_runtime.h>
#include <cuda_fp16.h>
#include <cstdint>
#include <math.h>

// Problem constants
#define NUM_E   16
#define T_TOK   8192
#define DIN     1024
#define DOUT    4096
#define TPE     512

// GEMM tiling
#define BM 128
#define BN 128
#define BK 32
#define KIT (DIN / BK)       // 32

// SMEM layout: A 4-stage cp.async ring (fp16), B 2-stage STS ring (fp16)
#define A_STRIDE 80          // bytes per m-row (32 halves + 16B pad) -> conflict-free ldmatrix
#define B_STRIDE 272         // bytes per k-row (128 halves + 16B pad)
#define AH_BYTES (BM * A_STRIDE)           // 10240
#define BH_BYTES (BK * B_STRIDE)           // 8704
#define SM_B0    (4 * AH_BYTES)            // 40960
#define SMEM_TOTAL (SM_B0 + 2 * BH_BYTES)  // 58368

// Scratch (allocation-free rule: __device__ global)
__device__ __half g_xh[(size_t)T_TOK * DIN];   // 16MB LN output fp16

// ---------------- helpers ----------------
__device__ __forceinline__ uint32_t smem_u32(const void* p) {
    uint32_t a;
    asm("{ .reg .u64 t; cvta.to.shared.u64 t, %1; cvt.u32.u64 %0, t; }"
        : "=r"(a) : "l"(p));
    return a;
}

#define CP_ASYNC16(dst, src) \
    asm volatile("cp.async.cg.shared.global [%0], [%1], 16;" \
        :: "r"(dst), "l"(src))
#define CP_COMMIT() asm volatile("cp.async.commit_group;" ::: "memory")
#define CP_WAIT2()  asm volatile("cp.async.wait_group 2;" ::: "memory")

#define LDMATRIX_X4(r0, r1, r2, r3, addr) \
    asm volatile("ldmatrix.sync.aligned.m8n8.x4.shared.b16 {%0,%1,%2,%3}, [%4];" \
        : "=r"(r0), "=r"(r1), "=r"(r2), "=r"(r3) : "r"(addr))
#define LDMATRIX_X4_T(r0, r1, r2, r3, addr) \
    asm volatile("ldmatrix.sync.aligned.m8n8.x4.trans.shared.b16 {%0,%1,%2,%3}, [%4];" \
        : "=r"(r0), "=r"(r1), "=r"(r2), "=r"(r3) : "r"(addr))

__device__ __forceinline__ void mma_f16(float* d, const uint32_t* a, const uint32_t* b) {
    asm volatile(
        "mma.sync.aligned.m16n8k16.row.col.f32.f16.f16.f32 "
        "{%0,%1,%2,%3}, {%4,%5,%6,%7}, {%8,%9}, {%0,%1,%2,%3};"
        : "+f"(d[0]), "+f"(d[1]), "+f"(d[2]), "+f"(d[3])
        : "r"(a[0]), "r"(a[1]), "r"(a[2]), "r"(a[3]), "r"(b[0]), "r"(b[1]));
}

__device__ __forceinline__ float tanh_fast(float x) {
    float r;
    asm("tanh.approx.f32 %0, %1;" : "=f"(r) : "f"(x));
    return r;
}
__device__ __forceinline__ float gelu_tanh(float x) {
    const float c = 0.7978845608028654f;
    float t = tanh_fast(c * (x + 0.044715f * x * x * x));
    return 0.5f * x * (1.0f + t);
}

// ---------------- LayerNorm: warp-per-token, no block sync ----------------
__global__ __launch_bounds__(256) void ln_kernel(
    const float* __restrict__ x,
    const float* __restrict__ gamma,
    const float* __restrict__ beta)
{
    const int tid  = threadIdx.x;
    const int wid  = tid >> 5;
    const int lane = tid & 31;
    const int t = blockIdx.x * 8 + wid;
    const int e = t >> 9;

    const float4* xp = reinterpret_cast<const float4*>(x + (size_t)t * DIN);
    float4 v[8];
    float s = 0.0f, q = 0.0f;
    #pragma unroll
    for (int i = 0; i < 8; ++i) {
        v[i] = xp[i * 32 + lane];
        s += v[i].x + v[i].y + v[i].z + v[i].w;
        q += v[i].x * v[i].x + v[i].y * v[i].y + v[i].z * v[i].z + v[i].w * v[i].w;
    }
    #pragma unroll
    for (int o = 16; o; o >>= 1) {
        s += __shfl_xor_sync(0xFFFFFFFFu, s, o);
        q += __shfl_xor_sync(0xFFFFFFFFu, q, o);
    }
    const float mean = s * (1.0f / DIN);
    const float var  = q * (1.0f / DIN) - mean * mean;
    const float rs   = rsqrtf(var + 1e-5f);

    const float4* gp = reinterpret_cast<const float4*>(gamma + (size_t)e * DIN);
    const float4* bp = reinterpret_cast<const float4*>(beta  + (size_t)e * DIN);
    uint2* op = reinterpret_cast<uint2*>(g_xh + (size_t)t * DIN);
    #pragma unroll
    for (int i = 0; i < 8; ++i) {
        const float4 g = gp[i * 32 + lane];
        const float4 b = bp[i * 32 + lane];
        __half2 h0 = __floats2half2_rn((v[i].x - mean) * rs * g.x + b.x,
                                       (v[i].y - mean) * rs * g.y + b.y);
        __half2 h1 = __floats2half2_rn((v[i].z - mean) * rs * g.z + b.z,
                                       (v[i].w - mean) * rs * g.w + b.w);
        uint2 pack;
        pack.x = *reinterpret_cast<uint32_t*>(&h0);
        pack.y = *reinterpret_cast<uint32_t*>(&h1);
        op[i * 32 + lane] = pack;
    }
}

// ---------------- A stage loader (cp.async, fp16 from g_xh) ----------------
__device__ __forceinline__ void issue_stage_a(uint32_t su,
                                              const __half* __restrict__ xa,
                                              int k0, int tid)
{
    #pragma unroll
    for (int i = 0; i < 2; ++i) {
        const int c = tid + i * 256;
        const int m  = c >> 2;
        const int kc = c & 3;
        const __half* src = xa + (size_t)m * DIN + k0 + kc * 8;
        CP_ASYNC16(su + (uint32_t)(m * A_STRIDE + kc * 16), src);
    }
}

// ---------------- B prefetch: LDG fp32 -> regs ----------------
// stage = 32 k-rows x 128 n fp32; per thread 4 float4 (16 floats)
__device__ __forceinline__ void ldg_b(float4* pf, const float* __restrict__ wb,
                                      int k0, int tid)
{
    #pragma unroll
    for (int i = 0; i < 4; ++i) {
        const int c = tid + i * 256;         // 0..1023
        const int k  = c >> 5;
        const int cn = c & 31;
        pf[i] = *reinterpret_cast<const float4*>(wb + (size_t)(k0 + k) * DOUT + cn * 4);
    }
}

// ---------------- B commit: cvt fp32->fp16, STS ----------------
__device__ __forceinline__ void sts_b(uint32_t sbB, const float4* pf, int tid)
{
    #pragma unroll
    for (int i = 0; i < 4; ++i) {
        const int c = tid + i * 256;
        const int k  = c >> 5;
        const int cn = c & 31;
        __half2 h0 = __floats2half2_rn(pf[i].x, pf[i].y);
        __half2 h1 = __floats2half2_rn(pf[i].z, pf[i].w);
        uint32_t lo = *reinterpret_cast<uint32_t*>(&h0);
        uint32_t hi = *reinterpret_cast<uint32_t*>(&h1);
        asm volatile("st.shared.v2.b32 [%0], {%1, %2};"
            :: "r"(sbB + (uint32_t)(k * B_STRIDE + cn * 8)), "r"(lo), "r"(hi)
            : "memory");
    }
}

// ---------------- grouped GEMM fp16 + bias + GELU ----------------
__global__ __launch_bounds__(256, 2) void moe_gemm_kernel(
    const float* __restrict__ W,
    const float* __restrict__ bias,
    float* __restrict__ out)
{
    extern __shared__ char smem[];
    const uint32_t sbase = smem_u32(smem);

    const int tid  = threadIdx.x;
    const int wid  = tid >> 5;
    const int lane = tid & 31;
    const int g    = lane >> 2;
    const int c    = lane & 3;

    const int warp_m = (wid >> 2) * 64;
    const int warp_n = (wid & 3) * 32;

    const int bid = blockIdx.x;
    const int e   = bid >> 7;
    const int r   = bid & 127;
    const int mt_ = r & 3;                // mt fastest: 4 CTAs share W slice in L2
    const int nt_ = r >> 2;
    const int tok0 = e * TPE + mt_ * BM;
    const int n0   = nt_ * BN;

    const __half* xa = g_xh + (size_t)tok0 * DIN;
    const float*  wb = W + (size_t)e * DIN * DOUT + n0;

    const int lmat = lane >> 3;
    const int lrow = lane & 7;
    const uint32_t aoff = (uint32_t)(((lmat & 1) * 8 + lrow) * A_STRIDE + (lmat >> 1) * 16);
    const uint32_t boff = (uint32_t)(((lmat & 1) * 8 + lrow) * B_STRIDE + (lmat >> 1) * 16);

    float acc[4][4][4];
    #pragma unroll
    for (int i = 0; i < 4; ++i)
        #pragma unroll
        for (int j = 0; j < 4; ++j)
            #pragma unroll
            for (int k = 0; k < 4; ++k)
                acc[i][j][k] = 0.0f;

    float4 pf0[4], pf1[4];

    // Prologue: B(0) -> Bsm0 immediately; A(0..2) in flight; B(1) -> pf0
    ldg_b(pf0, wb, 0, tid);
    #pragma unroll
    for (int s = 0; s < 3; ++s) {
        issue_stage_a(sbase + s * AH_BYTES, xa, s * BK, tid);
        CP_COMMIT();
    }
    sts_b(sbase + SM_B0, pf0, tid);
    ldg_b(pf0, wb, BK, tid);
    CP_WAIT2();
    __syncthreads();

    #pragma unroll 2
    for (int it = 0; it < KIT; ++it) {
        // A prefetch stage it+3
        if (it + 3 < KIT) {
            issue_stage_a(sbase + (uint32_t)(((it + 3) & 3) * AH_BYTES),
                          xa, (it + 3) * BK, tid);
        }
        CP_COMMIT();

        // commit B(it+1) into the ping-pong buffer consumed next iteration
        float4* pfCur = (it & 1) ? pf1 : pf0;
        float4* pfNxt = (it & 1) ? pf0 : pf1;
        if (it + 1 < KIT)
            sts_b(sbase + SM_B0 + (uint32_t)(((it + 1) & 1) * BH_BYTES), pfCur, tid);
        if (it + 2 < KIT)
            ldg_b(pfNxt, wb, (it + 2) * BK, tid);

        const uint32_t suA = sbase + (uint32_t)((it & 3) * AH_BYTES)
                           + (uint32_t)(warp_m * A_STRIDE) + aoff;
        const uint32_t suB = sbase + SM_B0 + (uint32_t)((it & 1) * BH_BYTES)
                           + (uint32_t)(warp_n * 2) + boff;

        #pragma unroll
        for (int ks = 0; ks < 2; ++ks) {
            uint32_t afr[4][4];
            #pragma unroll
            for (int mt = 0; mt < 4; ++mt)
                LDMATRIX_X4(afr[mt][0], afr[mt][1], afr[mt][2], afr[mt][3],
                            suA + (uint32_t)(mt * 16 * A_STRIDE + ks * 32));
            uint32_t bfr[2][4];
            #pragma unroll
            for (int nb = 0; nb < 2; ++nb)
                LDMATRIX_X4_T(bfr[nb][0], bfr[nb][1], bfr[nb][2], bfr[nb][3],
                              suB + (uint32_t)(ks * 16 * B_STRIDE + nb * 32));
            #pragma unroll
            for (int mt = 0; mt < 4; ++mt)
                #pragma unroll
                for (int nt = 0; nt < 4; ++nt)
                    mma_f16(acc[mt][nt], afr[mt], &bfr[nt >> 1][(nt & 1) * 2]);
        }

        CP_WAIT2();      // A(it+1) landed
        __syncthreads(); // Bsm[it&1] reads done; Bsm[(it+1)&1] STS visible
    }

    // ---------------- epilogue: bias + tanh-GELU + store ----------------
    const float* bptr = bias + (size_t)e * DOUT + n0 + warp_n;
    float2 bv[4];
    #pragma unroll
    for (int nt = 0; nt < 4; ++nt)
        bv[nt] = *(const float2*)(bptr + nt * 8 + 2 * c);

    #pragma unroll
    for (int mt = 0; mt < 4; ++mt) {
        const int row0 = tok0 + warp_m + mt * 16 + g;
        float* o0 = out + (size_t)row0 * DOUT + n0 + warp_n;
        float* o1 = o0 + (size_t)8 * DOUT;
        #pragma unroll
        for (int nt = 0; nt < 4; ++nt) {
            float2 v0, v1;
            v0.x = gelu_tanh(acc[mt][nt][0] + bv[nt].x);
            v0.y = gelu_tanh(acc[mt][nt][1] + bv[nt].y);
            v1.x = gelu_tanh(acc[mt][nt][2] + bv[nt].x);
            v1.y = gelu_tanh(acc[mt][nt][3] + bv[nt].y);
            *(float2*)(o0 + nt * 8 + 2 * c) = v0;
            *(float2*)(o1 + nt * 8 + 2 * c) = v1;
        }
    }
}

// ---------------- launch ----------------
extern "C" void kernel_launch(void* const* d_in, const int* in_sizes, int n_in,
                              void* d_out, int out_size) {
    (void)in_sizes; (void)n_in; (void)out_size;
    const float* x     = (const float*)d_in[0];
    // d_in[1] = expert_frequency (balanced; reference ignores it too)
    const float* gamma = (const float*)d_in[2];
    const float* beta  = (const float*)d_in[3];
    const float* W     = (const float*)d_in[4];
    const float* b     = (const float*)d_in[5];
    float* out = (float*)d_out;

    cudaFuncSetAttribute(moe_gemm_kernel,
                         cudaFuncAttributeMaxDynamicSharedMemorySize, SMEM_TOTAL);

    ln_kernel<<<T_TOK / 8, 256>>>(x, gamma, beta);
    moe_gemm_kernel<<<NUM_E * 4 * 32, 256, SMEM_TOTAL>>>(W, b, out);
}

// round 14
// speedup vs baseline: 1.5988x; 1.0604x over previous
#include <cuda_runtime.h>
#include <cuda_fp16.h>
#include <cstdint>
#include <math.h>

// Problem constants
#define NUM_E   16
#define T_TOK   8192
#define DIN     1024
#define DOUT    4096
#define TPE     512

// GEMM tiling
#define BM 128
#define BN 128
#define BK 32
#define KIT (DIN / BK)       // 32

// SMEM layout: A 4-stage cp.async ring (fp16), B 2-stage STS ring (fp16)
#define A_STRIDE 80          // bytes per m-row (32 halves + 16B pad) -> conflict-free ldmatrix
#define B_STRIDE 272         // bytes per k-row (128 halves + 16B pad)
#define AH_BYTES (BM * A_STRIDE)           // 10240
#define BH_BYTES (BK * B_STRIDE)           // 8704
#define SM_B0    (4 * AH_BYTES)            // 40960
#define SMEM_TOTAL (SM_B0 + 2 * BH_BYTES)  // 58368

// Scratch (allocation-free rule: __device__ global)
__device__ __half g_xh[(size_t)T_TOK * DIN];   // 16MB LN output fp16

// ---------------- helpers ----------------
__device__ __forceinline__ uint32_t smem_u32(const void* p) {
    uint32_t a;
    asm("{ .reg .u64 t; cvta.to.shared.u64 t, %1; cvt.u32.u64 %0, t; }"
        : "=r"(a) : "l"(p));
    return a;
}

#define CP_ASYNC16(dst, src) \
    asm volatile("cp.async.cg.shared.global [%0], [%1], 16;" \
        :: "r"(dst), "l"(src))
#define CP_COMMIT() asm volatile("cp.async.commit_group;" ::: "memory")
#define CP_WAIT2()  asm volatile("cp.async.wait_group 2;" ::: "memory")

#define LDMATRIX_X4(r0, r1, r2, r3, addr) \
    asm volatile("ldmatrix.sync.aligned.m8n8.x4.shared.b16 {%0,%1,%2,%3}, [%4];" \
        : "=r"(r0), "=r"(r1), "=r"(r2), "=r"(r3) : "r"(addr))
#define LDMATRIX_X4_T(r0, r1, r2, r3, addr) \
    asm volatile("ldmatrix.sync.aligned.m8n8.x4.trans.shared.b16 {%0,%1,%2,%3}, [%4];" \
        : "=r"(r0), "=r"(r1), "=r"(r2), "=r"(r3) : "r"(addr))

__device__ __forceinline__ void mma_f16(float* d, const uint32_t* a, const uint32_t* b) {
    asm volatile(
        "mma.sync.aligned.m16n8k16.row.col.f32.f16.f16.f32 "
        "{%0,%1,%2,%3}, {%4,%5,%6,%7}, {%8,%9}, {%0,%1,%2,%3};"
        : "+f"(d[0]), "+f"(d[1]), "+f"(d[2]), "+f"(d[3])
        : "r"(a[0]), "r"(a[1]), "r"(a[2]), "r"(a[3]), "r"(b[0]), "r"(b[1]));
}

__device__ __forceinline__ float tanh_fast(float x) {
    float r;
    asm("tanh.approx.f32 %0, %1;" : "=f"(r) : "f"(x));
    return r;
}
__device__ __forceinline__ float gelu_tanh(float x) {
    const float c = 0.7978845608028654f;
    float t = tanh_fast(c * (x + 0.044715f * x * x * x));
    return 0.5f * x * (1.0f + t);
}

// ---------------- LayerNorm: warp-per-token, no block sync ----------------
__global__ __launch_bounds__(256) void ln_kernel(
    const float* __restrict__ x,
    const float* __restrict__ gamma,
    const float* __restrict__ beta)
{
    const int tid  = threadIdx.x;
    const int wid  = tid >> 5;
    const int lane = tid & 31;
    const int t = blockIdx.x * 8 + wid;
    const int e = t >> 9;

    const float4* xp = reinterpret_cast<const float4*>(x + (size_t)t * DIN);
    float4 v[8];
    float s = 0.0f, q = 0.0f;
    #pragma unroll
    for (int i = 0; i < 8; ++i) {
        v[i] = xp[i * 32 + lane];
        s += v[i].x + v[i].y + v[i].z + v[i].w;
        q += v[i].x * v[i].x + v[i].y * v[i].y + v[i].z * v[i].z + v[i].w * v[i].w;
    }
    #pragma unroll
    for (int o = 16; o; o >>= 1) {
        s += __shfl_xor_sync(0xFFFFFFFFu, s, o);
        q += __shfl_xor_sync(0xFFFFFFFFu, q, o);
    }
    const float mean = s * (1.0f / DIN);
    const float var  = q * (1.0f / DIN) - mean * mean;
    const float rs   = rsqrtf(var + 1e-5f);

    const float4* gp = reinterpret_cast<const float4*>(gamma + (size_t)e * DIN);
    const float4* bp = reinterpret_cast<const float4*>(beta  + (size_t)e * DIN);
    uint2* op = reinterpret_cast<uint2*>(g_xh + (size_t)t * DIN);
    #pragma unroll
    for (int i = 0; i < 8; ++i) {
        const float4 g = gp[i * 32 + lane];
        const float4 b = bp[i * 32 + lane];
        __half2 h0 = __floats2half2_rn((v[i].x - mean) * rs * g.x + b.x,
                                       (v[i].y - mean) * rs * g.y + b.y);
        __half2 h1 = __floats2half2_rn((v[i].z - mean) * rs * g.z + b.z,
                                       (v[i].w - mean) * rs * g.w + b.w);
        uint2 pack;
        pack.x = *reinterpret_cast<uint32_t*>(&h0);
        pack.y = *reinterpret_cast<uint32_t*>(&h1);
        op[i * 32 + lane] = pack;
    }
}

// ---------------- A stage loader (cp.async, fp16 from g_xh) ----------------
__device__ __forceinline__ void issue_stage_a(uint32_t su,
                                              const __half* __restrict__ xa,
                                              int k0, int tid)
{
    #pragma unroll
    for (int i = 0; i < 2; ++i) {
        const int c = tid + i * 256;
        const int m  = c >> 2;
        const int kc = c & 3;
        const __half* src = xa + (size_t)m * DIN + k0 + kc * 8;
        CP_ASYNC16(su + (uint32_t)(m * A_STRIDE + kc * 16), src);
    }
}

// ---------------- B prefetch: LDG fp32 -> regs (single 16-reg buffer) ----------------
__device__ __forceinline__ void ldg_b(float4* pf, const float* __restrict__ wb,
                                      int k0, int tid)
{
    #pragma unroll
    for (int i = 0; i < 4; ++i) {
        const int c = tid + i * 256;         // 0..1023
        const int k  = c >> 5;
        const int cn = c & 31;
        pf[i] = *reinterpret_cast<const float4*>(wb + (size_t)(k0 + k) * DOUT + cn * 4);
    }
}

// ---------------- B commit: cvt fp32->fp16, STS ----------------
__device__ __forceinline__ void sts_b(uint32_t sbB, const float4* pf, int tid)
{
    #pragma unroll
    for (int i = 0; i < 4; ++i) {
        const int c = tid + i * 256;
        const int k  = c >> 5;
        const int cn = c & 31;
        __half2 h0 = __floats2half2_rn(pf[i].x, pf[i].y);
        __half2 h1 = __floats2half2_rn(pf[i].z, pf[i].w);
        uint32_t lo = *reinterpret_cast<uint32_t*>(&h0);
        uint32_t hi = *reinterpret_cast<uint32_t*>(&h1);
        asm volatile("st.shared.v2.b32 [%0], {%1, %2};"
            :: "r"(sbB + (uint32_t)(k * B_STRIDE + cn * 8)), "r"(lo), "r"(hi)
            : "memory");
    }
}

// ---------------- grouped GEMM fp16 + bias + GELU ----------------
__global__ __launch_bounds__(256, 2) void moe_gemm_kernel(
    const float* __restrict__ W,
    const float* __restrict__ bias,
    float* __restrict__ out)
{
    extern __shared__ char smem[];
    const uint32_t sbase = smem_u32(smem);

    const int tid  = threadIdx.x;
    const int wid  = tid >> 5;
    const int lane = tid & 31;
    const int g    = lane >> 2;
    const int c    = lane & 3;

    const int warp_m = (wid >> 2) * 64;
    const int warp_n = (wid & 3) * 32;

    const int bid = blockIdx.x;
    const int e   = bid >> 7;
    const int r   = bid & 127;
    const int mt_ = r & 3;                // mt fastest: 4 CTAs share W slice in L2
    const int nt_ = r >> 2;
    const int tok0 = e * TPE + mt_ * BM;
    const int n0   = nt_ * BN;

    const __half* xa = g_xh + (size_t)tok0 * DIN;
    const float*  wb = W + (size_t)e * DIN * DOUT + n0;

    const int lmat = lane >> 3;
    const int lrow = lane & 7;
    const uint32_t aoff = (uint32_t)(((lmat & 1) * 8 + lrow) * A_STRIDE + (lmat >> 1) * 16);
    const uint32_t boff = (uint32_t)(((lmat & 1) * 8 + lrow) * B_STRIDE + (lmat >> 1) * 16);

    float acc[4][4][4];
    #pragma unroll
    for (int i = 0; i < 4; ++i)
        #pragma unroll
        for (int j = 0; j < 4; ++j)
            #pragma unroll
            for (int k = 0; k < 4; ++k)
                acc[i][j][k] = 0.0f;

    float4 pf[4];   // single B prefetch buffer (16 regs)

    // Prologue: B(0) -> Bsm0; A(0..2) in flight; B(1) -> pf
    ldg_b(pf, wb, 0, tid);
    #pragma unroll
    for (int s = 0; s < 3; ++s) {
        issue_stage_a(sbase + s * AH_BYTES, xa, s * BK, tid);
        CP_COMMIT();
    }
    sts_b(sbase + SM_B0, pf, tid);
    ldg_b(pf, wb, BK, tid);
    CP_WAIT2();
    __syncthreads();

    for (int it = 0; it < KIT; ++it) {
        // A prefetch stage it+3
        if (it + 3 < KIT) {
            issue_stage_a(sbase + (uint32_t)(((it + 3) & 3) * AH_BYTES),
                          xa, (it + 3) * BK, tid);
        }
        CP_COMMIT();

        // commit B(it+1) from pf, then refill pf with B(it+2)
        // (WAR on pf registers: STS reads at issue, LDG writeback follows)
        if (it + 1 < KIT)
            sts_b(sbase + SM_B0 + (uint32_t)(((it + 1) & 1) * BH_BYTES), pf, tid);
        if (it + 2 < KIT)
            ldg_b(pf, wb, (it + 2) * BK, tid);

        const uint32_t suA = sbase + (uint32_t)((it & 3) * AH_BYTES)
                           + (uint32_t)(warp_m * A_STRIDE) + aoff;
        const uint32_t suB = sbase + SM_B0 + (uint32_t)((it & 1) * BH_BYTES)
                           + (uint32_t)(warp_n * 2) + boff;

        #pragma unroll
        for (int ks = 0; ks < 2; ++ks) {
            uint32_t afr[4][4];
            #pragma unroll
            for (int mt = 0; mt < 4; ++mt)
                LDMATRIX_X4(afr[mt][0], afr[mt][1], afr[mt][2], afr[mt][3],
                            suA + (uint32_t)(mt * 16 * A_STRIDE + ks * 32));
            uint32_t bfr[2][4];
            #pragma unroll
            for (int nb = 0; nb < 2; ++nb)
                LDMATRIX_X4_T(bfr[nb][0], bfr[nb][1], bfr[nb][2], bfr[nb][3],
                              suB + (uint32_t)(ks * 16 * B_STRIDE + nb * 32));
            #pragma unroll
            for (int mt = 0; mt < 4; ++mt)
                #pragma unroll
                for (int nt = 0; nt < 4; ++nt)
                    mma_f16(acc[mt][nt], afr[mt], &bfr[nt >> 1][(nt & 1) * 2]);
        }

        CP_WAIT2();      // A(it+1) landed
        __syncthreads(); // Bsm[it&1] reads done; Bsm[(it+1)&1] STS visible
    }

    // ---------------- epilogue: bias + tanh-GELU + store ----------------
    const float* bptr = bias + (size_t)e * DOUT + n0 + warp_n;
    float2 bv[4];
    #pragma unroll
    for (int nt = 0; nt < 4; ++nt)
        bv[nt] = *(const float2*)(bptr + nt * 8 + 2 * c);

    #pragma unroll
    for (int mt = 0; mt < 4; ++mt) {
        const int row0 = tok0 + warp_m + mt * 16 + g;
        float* o0 = out + (size_t)row0 * DOUT + n0 + warp_n;
        float* o1 = o0 + (size_t)8 * DOUT;
        #pragma unroll
        for (int nt = 0; nt < 4; ++nt) {
            float2 v0, v1;
            v0.x = gelu_tanh(acc[mt][nt][0] + bv[nt].x);
            v0.y = gelu_tanh(acc[mt][nt][1] + bv[nt].y);
            v1.x = gelu_tanh(acc[mt][nt][2] + bv[nt].x);
            v1.y = gelu_tanh(acc[mt][nt][3] + bv[nt].y);
            *(float2*)(o0 + nt * 8 + 2 * c) = v0;
            *(float2*)(o1 + nt * 8 + 2 * c) = v1;
        }
    }
}

// ---------------- launch ----------------
extern "C" void kernel_launch(void* const* d_in, const int* in_sizes, int n_in,
                              void* d_out, int out_size) {
    (void)in_sizes; (void)n_in; (void)out_size;
    const float* x     = (const float*)d_in[0];
    // d_in[1] = expert_frequency (balanced; reference ignores it too)
    const float* gamma = (const float*)d_in[2];
    const float* beta  = (const float*)d_in[3];
    const float* W     = (const float*)d_in[4];
    const float* b     = (const float*)d_in[5];
    float* out = (float*)d_out;

    cudaFuncSetAttribute(moe_gemm_kernel,
                         cudaFuncAttributeMaxDynamicSharedMemorySize, SMEM_TOTAL);

    ln_kernel<<<T_TOK / 8, 256>>>(x, gamma, beta);
    moe_gemm_kernel<<<NUM_E * 4 * 32, 256, SMEM_TOTAL>>>(W, b, out);
}

// round 17
// speedup vs baseline: 1.6271x; 1.0177x over previous
#include <cuda_runtime.h>
#include <cuda_fp16.h>
#include <cstdint>
#include <math.h>

// Problem constants
#define NUM_E   16
#define T_TOK   8192
#define DIN     1024
#define DOUT    4096
#define TPE     512

// GEMM tiling
#define BM 128
#define BN 128
#define BK 64
#define KIT (DIN / BK)       // 16

// SMEM: A 3-stage cp.async ring (fp16), B 2-buffer STS ping-pong (fp16)
#define A_STRIDE 144         // 64 halves = 128B payload + 16B pad (9 mod 8 -> conflict-free)
#define B_STRIDE 272         // 128 halves = 256B payload + 16B pad
#define AH_BYTES (BM * A_STRIDE)           // 18432
#define BH_BYTES (BK * B_STRIDE)           // 17408
#define SM_B0    (3 * AH_BYTES)            // 55296
#define SMEM_TOTAL (SM_B0 + 2 * BH_BYTES)  // 90112

// Scratch (allocation-free rule: __device__ global)
__device__ __half g_xh[(size_t)T_TOK * DIN];   // 16MB LN output fp16

// ---------------- helpers ----------------
__device__ __forceinline__ uint32_t smem_u32(const void* p) {
    uint32_t a;
    asm("{ .reg .u64 t; cvta.to.shared.u64 t, %1; cvt.u32.u64 %0, t; }"
        : "=r"(a) : "l"(p));
    return a;
}

#define CP_ASYNC16(dst, src) \
    asm volatile("cp.async.cg.shared.global [%0], [%1], 16;" \
        :: "r"(dst), "l"(src))
#define CP_COMMIT() asm volatile("cp.async.commit_group;" ::: "memory")
#define CP_WAIT1()  asm volatile("cp.async.wait_group 1;" ::: "memory")

#define LDMATRIX_X4(r0, r1, r2, r3, addr) \
    asm volatile("ldmatrix.sync.aligned.m8n8.x4.shared.b16 {%0,%1,%2,%3}, [%4];" \
        : "=r"(r0), "=r"(r1), "=r"(r2), "=r"(r3) : "r"(addr))
#define LDMATRIX_X4_T(r0, r1, r2, r3, addr) \
    asm volatile("ldmatrix.sync.aligned.m8n8.x4.trans.shared.b16 {%0,%1,%2,%3}, [%4];" \
        : "=r"(r0), "=r"(r1), "=r"(r2), "=r"(r3) : "r"(addr))

__device__ __forceinline__ void mma_f16(float* d, const uint32_t* a, const uint32_t* b) {
    asm volatile(
        "mma.sync.aligned.m16n8k16.row.col.f32.f16.f16.f32 "
        "{%0,%1,%2,%3}, {%4,%5,%6,%7}, {%8,%9}, {%0,%1,%2,%3};"
        : "+f"(d[0]), "+f"(d[1]), "+f"(d[2]), "+f"(d[3])
        : "r"(a[0]), "r"(a[1]), "r"(a[2]), "r"(a[3]), "r"(b[0]), "r"(b[1]));
}

__device__ __forceinline__ float tanh_fast(float x) {
    float r;
    asm("tanh.approx.f32 %0, %1;" : "=f"(r) : "f"(x));
    return r;
}
__device__ __forceinline__ float gelu_tanh(float x) {
    const float c = 0.7978845608028654f;
    float t = tanh_fast(c * (x + 0.044715f * x * x * x));
    return 0.5f * x * (1.0f + t);
}

// ---------------- LayerNorm: warp-per-token, no block sync ----------------
__global__ __launch_bounds__(256) void ln_kernel(
    const float* __restrict__ x,
    const float* __restrict__ gamma,
    const float* __restrict__ beta)
{
    const int tid  = threadIdx.x;
    const int wid  = tid >> 5;
    const int lane = tid & 31;
    const int t = blockIdx.x * 8 + wid;
    const int e = t >> 9;

    const float4* xp = reinterpret_cast<const float4*>(x + (size_t)t * DIN);
    float4 v[8];
    float s = 0.0f, q = 0.0f;
    #pragma unroll
    for (int i = 0; i < 8; ++i) {
        v[i] = xp[i * 32 + lane];
        s += v[i].x + v[i].y + v[i].z + v[i].w;
        q += v[i].x * v[i].x + v[i].y * v[i].y + v[i].z * v[i].z + v[i].w * v[i].w;
    }
    #pragma unroll
    for (int o = 16; o; o >>= 1) {
        s += __shfl_xor_sync(0xFFFFFFFFu, s, o);
        q += __shfl_xor_sync(0xFFFFFFFFu, q, o);
    }
    const float mean = s * (1.0f / DIN);
    const float var  = q * (1.0f / DIN) - mean * mean;
    const float rs   = rsqrtf(var + 1e-5f);

    const float4* gp = reinterpret_cast<const float4*>(gamma + (size_t)e * DIN);
    const float4* bp = reinterpret_cast<const float4*>(beta  + (size_t)e * DIN);
    uint2* op = reinterpret_cast<uint2*>(g_xh + (size_t)t * DIN);
    #pragma unroll
    for (int i = 0; i < 8; ++i) {
        const float4 g = gp[i * 32 + lane];
        const float4 b = bp[i * 32 + lane];
        __half2 h0 = __floats2half2_rn((v[i].x - mean) * rs * g.x + b.x,
                                       (v[i].y - mean) * rs * g.y + b.y);
        __half2 h1 = __floats2half2_rn((v[i].z - mean) * rs * g.z + b.z,
                                       (v[i].w - mean) * rs * g.w + b.w);
        uint2 pack;
        pack.x = *reinterpret_cast<uint32_t*>(&h0);
        pack.y = *reinterpret_cast<uint32_t*>(&h1);
        op[i * 32 + lane] = pack;
    }
}

// ---------------- A stage loader (cp.async fp16): 128 rows x 64 halves ----------------
__device__ __forceinline__ void issue_stage_a(uint32_t su,
                                              const __half* __restrict__ xa,
                                              int k0, int tid)
{
    #pragma unroll
    for (int i = 0; i < 4; ++i) {
        const int c = tid + i * 256;         // 0..1023 chunks of 16B
        const int m  = c >> 3;
        const int kc = c & 7;
        const __half* src = xa + (size_t)m * DIN + k0 + kc * 8;
        CP_ASYNC16(su + (uint32_t)(m * A_STRIDE + kc * 16), src);
    }
}

// ---------------- B half-stage prefetch: 32 k-rows fp32 -> 16 regs ----------------
__device__ __forceinline__ void ldg_bh(float4* pf, const float* __restrict__ wb,
                                       int k0, int tid)
{
    #pragma unroll
    for (int i = 0; i < 4; ++i) {
        const int c = tid + i * 256;         // 0..1023
        const int k  = c >> 5;               // 0..31
        const int cn = c & 31;
        pf[i] = *reinterpret_cast<const float4*>(wb + (size_t)(k0 + k) * DOUT + cn * 4);
    }
}

// ---------------- B half-stage commit: cvt fp32->fp16, STS (rows rowoff..rowoff+31) ----
__device__ __forceinline__ void sts_bh(uint32_t sbB, int rowoff, const float4* pf, int tid)
{
    #pragma unroll
    for (int i = 0; i < 4; ++i) {
        const int c = tid + i * 256;
        const int k  = (c >> 5) + rowoff;
        const int cn = c & 31;
        __half2 h0 = __floats2half2_rn(pf[i].x, pf[i].y);
        __half2 h1 = __floats2half2_rn(pf[i].z, pf[i].w);
        uint32_t lo = *reinterpret_cast<uint32_t*>(&h0);
        uint32_t hi = *reinterpret_cast<uint32_t*>(&h1);
        asm volatile("st.shared.v2.b32 [%0], {%1, %2};"
            :: "r"(sbB + (uint32_t)(k * B_STRIDE + cn * 8)), "r"(lo), "r"(hi)
            : "memory");
    }
}

// ---------------- compute 2 k-steps (32 k) from given SMEM offsets ----------------
__device__ __forceinline__ void compute_ks2(float acc[4][4][4],
                                            uint32_t suA, uint32_t suB,
                                            int ksbase)
{
    #pragma unroll
    for (int ks = ksbase; ks < ksbase + 2; ++ks) {
        uint32_t afr[4][4];
        #pragma unroll
        for (int mt = 0; mt < 4; ++mt)
            LDMATRIX_X4(afr[mt][0], afr[mt][1], afr[mt][2], afr[mt][3],
                        suA + (uint32_t)(mt * 16 * A_STRIDE + ks * 32));
        uint32_t bfr[2][4];
        #pragma unroll
        for (int nb = 0; nb < 2; ++nb)
            LDMATRIX_X4_T(bfr[nb][0], bfr[nb][1], bfr[nb][2], bfr[nb][3],
                          suB + (uint32_t)(ks * 16 * B_STRIDE + nb * 32));
        #pragma unroll
        for (int mt = 0; mt < 4; ++mt)
            #pragma unroll
            for (int nt = 0; nt < 4; ++nt)
                mma_f16(acc[mt][nt], afr[mt], &bfr[nt >> 1][(nt & 1) * 2]);
    }
}

// ---------------- grouped GEMM fp16 + bias + GELU ----------------
__global__ __launch_bounds__(256, 2) void moe_gemm_kernel(
    const float* __restrict__ W,
    const float* __restrict__ bias,
    float* __restrict__ out)
{
    extern __shared__ char smem[];
    const uint32_t sbase = smem_u32(smem);

    const int tid  = threadIdx.x;
    const int wid  = tid >> 5;
    const int lane = tid & 31;
    const int g    = lane >> 2;
    const int c    = lane & 3;

    const int warp_m = (wid >> 2) * 64;
    const int warp_n = (wid & 3) * 32;

    const int bid = blockIdx.x;
    const int e   = bid >> 7;
    const int r   = bid & 127;
    const int mt_ = r & 3;                // mt fastest: 4 CTAs share W slice in L2
    const int nt_ = r >> 2;
    const int tok0 = e * TPE + mt_ * BM;
    const int n0   = nt_ * BN;

    const __half* xa = g_xh + (size_t)tok0 * DIN;
    const float*  wb = W + (size_t)e * DIN * DOUT + n0;

    const int lmat = lane >> 3;
    const int lrow = lane & 7;
    const uint32_t aoff = (uint32_t)(((lmat & 1) * 8 + lrow) * A_STRIDE + (lmat >> 1) * 16);
    const uint32_t boff = (uint32_t)(((lmat & 1) * 8 + lrow) * B_STRIDE + (lmat >> 1) * 16);

    float acc[4][4][4];
    #pragma unroll
    for (int i = 0; i < 4; ++i)
        #pragma unroll
        for (int j = 0; j < 4; ++j)
            #pragma unroll
            for (int k = 0; k < 4; ++k)
                acc[i][j][k] = 0.0f;

    float4 pf[4];   // single 16-reg B half-stage buffer

    // Prologue: fill B buf0 (two halves), A stages 0,1 in flight, pf <- B(1).half0
    ldg_bh(pf, wb, 0, tid);                    // B0 rows 0-31
    issue_stage_a(sbase + 0 * AH_BYTES, xa, 0, tid);
    CP_COMMIT();
    sts_bh(sbase + SM_B0, 0, pf, tid);
    ldg_bh(pf, wb, 32, tid);                   // B0 rows 32-63
    issue_stage_a(sbase + 1 * AH_BYTES, xa, BK, tid);
    CP_COMMIT();
    sts_bh(sbase + SM_B0, 32, pf, tid);
    ldg_bh(pf, wb, BK, tid);                   // B1 rows 0-31 (for it=0)
    CP_WAIT1();
    __syncthreads();

    for (int it = 0; it < KIT; ++it) {
        // A prefetch stage it+2 (3-stage ring)
        if (it + 2 < KIT) {
            issue_stage_a(sbase + (uint32_t)(((it + 2) % 3) * AH_BYTES),
                          xa, (it + 2) * BK, tid);
        }
        CP_COMMIT();

        const uint32_t sbBn = sbase + SM_B0 + (uint32_t)(((it + 1) & 1) * BH_BYTES);
        // commit B(it+1).half0 from pf; refill pf with B(it+1).half1
        if (it + 1 < KIT) {
            sts_bh(sbBn, 0, pf, tid);
            ldg_bh(pf, wb, (it + 1) * BK + 32, tid);
        }

        const uint32_t suA = sbase + (uint32_t)((it % 3) * AH_BYTES)
                           + (uint32_t)(warp_m * A_STRIDE) + aoff;
        const uint32_t suB = sbase + SM_B0 + (uint32_t)((it & 1) * BH_BYTES)
                           + (uint32_t)(warp_n * 2) + boff;

        compute_ks2(acc, suA, suB, 0);       // k 0..31 of this stage

        // commit B(it+1).half1; refill pf with B(it+2).half0
        if (it + 1 < KIT) {
            sts_bh(sbBn, 32, pf, tid);
            if (it + 2 < KIT)
                ldg_bh(pf, wb, (it + 2) * BK, tid);
        }

        compute_ks2(acc, suA, suB, 2);       // k 32..63 of this stage

        CP_WAIT1();      // A(it+1) landed
        __syncthreads(); // B reads done; next-B STS visible
    }

    // ---------------- epilogue: bias + tanh-GELU + store ----------------
    const float* bptr = bias + (size_t)e * DOUT + n0 + warp_n;
    float2 bv[4];
    #pragma unroll
    for (int nt = 0; nt < 4; ++nt)
        bv[nt] = *(const float2*)(bptr + nt * 8 + 2 * c);

    #pragma unroll
    for (int mt = 0; mt < 4; ++mt) {
        const int row0 = tok0 + warp_m + mt * 16 + g;
        float* o0 = out + (size_t)row0 * DOUT + n0 + warp_n;
        float* o1 = o0 + (size_t)8 * DOUT;
        #pragma unroll
        for (int nt = 0; nt < 4; ++nt) {
            float2 v0, v1;
            v0.x = gelu_tanh(acc[mt][nt][0] + bv[nt].x);
            v0.y = gelu_tanh(acc[mt][nt][1] + bv[nt].y);
            v1.x = gelu_tanh(acc[mt][nt][2] + bv[nt].x);
            v1.y = gelu_tanh(acc[mt][nt][3] + bv[nt].y);
            *(float2*)(o0 + nt * 8 + 2 * c) = v0;
            *(float2*)(o1 + nt * 8 + 2 * c) = v1;
        }
    }
}

// ---------------- launch ----------------
extern "C" void kernel_launch(void* const* d_in, const int* in_sizes, int n_in,
                              void* d_out, int out_size) {
    (void)in_sizes; (void)n_in; (void)out_size;
    const float* x     = (const float*)d_in[0];
    // d_in[1] = expert_frequency (balanced; reference ignores it too)
    const float* gamma = (const float*)d_in[2];
    const float* beta  = (const float*)d_in[3];
    const float* W     = (const float*)d_in[4];
    const float* b     = (const float*)d_in[5];
    float* out = (float*)d_out;

    cudaFuncSetAttribute(moe_gemm_kernel,
                         cudaFuncAttributeMaxDynamicSharedMemorySize, SMEM_TOTAL);

    ln_kernel<<<T_TOK / 8, 256>>>(x, gamma, beta);
    moe_gemm_kernel<<<NUM_E * 4 * 32, 256, SMEM_TOTAL>>>(W, b, out);
}